// round 3
// baseline (speedup 1.0000x reference)
#include <cuda_runtime.h>

// ---------------------------------------------------------------------------
// NeuralSplineFlow3D fused kernel (fp32, FFMA2, 2 points/thread to amortize
// broadcast weight LDS over 4 FFMA2 each)
// ---------------------------------------------------------------------------

#define THREADS   128          // 2 columns per thread -> 256 points per CTA
#define COLS      256
#define PW        68           // smem pitch (floats) for 64-wide hidden weights
#define PO        80           // smem pitch (floats) for output weights
#define TBc       5.0f
#define MINc      0.001f
#define LOGZc     (-2.7568155996140194f)   // -1.5*log(2*pi)
#define DCONSTf   (0.5397424697f)          // log(exp(1-0.001)-1)

// smem layout (float offsets)
#define SM_WT     0                         // 4*64*68 = 17408
#define SM_WO     (SM_WT + 4*64*PW)         // 64*80   = 5120
#define SM_WIN    (SM_WO + 64*PO)           // 64
#define SM_BIN    (SM_WIN + 64)             // 64
#define SM_BBLK   (SM_BIN + 64)             // 256
#define SM_BOUT   (SM_BBLK + 256)           // 80
#define SM_H      (SM_BOUT + PO)            // 64*256 = 16384
#define SM_T      (SM_H + 64*COLS)          // 64*256 = 16384
#define SM_TOTALF (SM_T + 64*COLS)
#define SMEM_BYTES (SM_TOTALF * 4)          // ~223 KB

typedef unsigned long long u64;

static __device__ __forceinline__ u64 ffma2(u64 a, u64 b, u64 c) {
    u64 d;
    asm("fma.rn.f32x2 %0, %1, %2, %3;" : "=l"(d) : "l"(a), "l"(b), "l"(c));
    return d;
}
static __device__ __forceinline__ u64 pk2(float v) {
    u64 r;
    asm("mov.b64 %0, {%1, %1};" : "=l"(r) : "f"(v));
    return r;
}
static __device__ __forceinline__ void upk2(u64 v, float& lo, float& hi) {
    asm("mov.b64 {%0, %1}, %2;" : "=f"(lo), "=f"(hi) : "l"(v));
}

static __device__ __forceinline__ float softplusf(float x) {
    return fmaxf(x, 0.0f) + log1pf(__expf(-fabsf(x)));
}

// For both columns t0 and t0+128:
// dst[o][col] = bias[o] + sum_k act(in[k][col]) * Wt[k][o]; optional += into dst.
template<bool RELU, bool ADD>
static __device__ __forceinline__ void dense64_p2(const float* __restrict__ Wt,
                                                  const float* __restrict__ bias,
                                                  const float* __restrict__ inb,
                                                  float* __restrict__ dst, int t0) {
    u64 a0[32], a1[32];
#pragma unroll
    for (int q = 0; q < 32; ++q) {
        u64 b = *reinterpret_cast<const u64*>(bias + 2 * q);
        a0[q] = b;
        a1[q] = b;
    }
#pragma unroll 1
    for (int k = 0; k < 64; ++k) {
        float r0 = inb[(k << 8) + t0];
        float r1 = inb[(k << 8) + t0 + 128];
        if (RELU) { r0 = fmaxf(r0, 0.0f); r1 = fmaxf(r1, 0.0f); }
        u64 rr0 = pk2(r0);
        u64 rr1 = pk2(r1);
        const float* wr = Wt + k * PW;
#pragma unroll
        for (int q = 0; q < 16; ++q) {
            ulonglong2 w = *reinterpret_cast<const ulonglong2*>(wr + 4 * q);
            a0[2 * q]     = ffma2(rr0, w.x, a0[2 * q]);
            a1[2 * q]     = ffma2(rr1, w.x, a1[2 * q]);
            a0[2 * q + 1] = ffma2(rr0, w.y, a0[2 * q + 1]);
            a1[2 * q + 1] = ffma2(rr1, w.y, a1[2 * q + 1]);
        }
    }
#pragma unroll
    for (int q = 0; q < 32; ++q) {
        float lo0, hi0, lo1, hi1;
        upk2(a0[q], lo0, hi0);
        upk2(a1[q], lo1, hi1);
        int r0 = (2 * q) << 8, r1 = (2 * q + 1) << 8;
        if (ADD) {
            dst[r0 + t0]       += lo0;
            dst[r1 + t0]       += hi0;
            dst[r0 + t0 + 128] += lo1;
            dst[r1 + t0 + 128] += hi1;
        } else {
            dst[r0 + t0]       = lo0;
            dst[r1 + t0]       = hi0;
            dst[r0 + t0 + 128] = lo1;
            dst[r1 + t0 + 128] = hi1;
        }
    }
}

// 37 outputs (one spline dim, one column) into p[0..36]. No relu on input.
static __device__ __forceinline__ void denseOutHalf(const float* __restrict__ Wo,
                                                    const float* __restrict__ bias,
                                                    const float* __restrict__ inb,
                                                    int col, float* __restrict__ p) {
    u64 acc[18];
    float accs;
#pragma unroll
    for (int q = 0; q < 18; ++q)
        acc[q] = *reinterpret_cast<const u64*>(bias + 2 * q);
    accs = bias[36];
#pragma unroll 1
    for (int k = 0; k < 64; ++k) {
        float r = inb[(k << 8) + col];
        u64 rr = pk2(r);
        const float* wr = Wo + k * PO;
#pragma unroll
        for (int q = 0; q < 9; ++q) {
            ulonglong2 w = *reinterpret_cast<const ulonglong2*>(wr + 4 * q);
            acc[2 * q]     = ffma2(rr, w.x, acc[2 * q]);
            acc[2 * q + 1] = ffma2(rr, w.y, acc[2 * q + 1]);
        }
        accs = fmaf(r, wr[36], accs);
    }
#pragma unroll
    for (int q = 0; q < 18; ++q) upk2(acc[q], p[2 * q], p[2 * q + 1]);
    p[36] = accs;
}

// softmax(12 logits at p[B..B+11]) -> bins; optional bin search; left knot + size.
template<int B, bool CB>
static __device__ __forceinline__ void soft_knots(const float* __restrict__ p, float xc,
                                                  int& bin, float& left, float& sz) {
    float e[12];
    float m = p[B];
#pragma unroll
    for (int j = 1; j < 12; ++j) m = fmaxf(m, p[B + j]);
    float s = 0.0f;
#pragma unroll
    for (int j = 0; j < 12; ++j) { e[j] = __expf(p[B + j] - m); s += e[j]; }
    float cinv = 0.988f * __fdividef(1.0f, s);
#pragma unroll
    for (int j = 0; j < 12; ++j) e[j] = fmaf(e[j], cinv, MINc);

    if (CB) {
        bin = 0;
        float run = 0.0f;
#pragma unroll
        for (int j = 0; j < 12; ++j) {
            run += e[j];
            float ks = (j == 11) ? (TBc + 1e-6f) : fmaf(10.0f, run, -TBc);
            if (xc >= ks) ++bin;
        }
    }
    float run = 0.0f, prev = -TBc;
#pragma unroll
    for (int j = 0; j < 12; ++j) {
        run += e[j];
        float right = (j == 11) ? TBc : fmaf(10.0f, run, -TBc);
        if (j == bin) { left = prev; sz = right - prev; }
        prev = right;
    }
}

static __device__ __forceinline__ void rq_spline(const float* __restrict__ p, float xin,
                                                 float& yout, float& ladout) {
    bool inside = (xin >= -TBc) && (xin <= TBc);
    float xc = fminf(fmaxf(xin, -TBc), TBc);

    int bin = 0;
    float in_cw, in_w, in_ch, in_h;
    soft_knots<0,  true >(p, xc, bin, in_cw, in_w);
    soft_knots<12, false>(p, xc, bin, in_ch, in_h);

    float uk = DCONSTf, uk1 = DCONSTf;
#pragma unroll
    for (int j = 1; j <= 12; ++j) {
        float v = p[23 + j];
        if (j == bin)     uk  = v;
        if (j == bin + 1) uk1 = v;
    }
    float dk  = MINc + softplusf(uk);
    float dk1 = MINc + softplusf(uk1);

    float invw  = __fdividef(1.0f, in_w);
    float delta = in_h * invw;
    float theta = (xc - in_cw) * invw;
    float om    = 1.0f - theta;
    float t1m   = theta * om;
    float th2   = theta * theta;
    float num   = in_h * (delta * th2 + dk * t1m);
    float den   = delta + (dk + dk1 - 2.0f * delta) * t1m;
    float y     = in_ch + __fdividef(num, den);
    float dnum  = (delta * delta) * (dk1 * th2 + 2.0f * delta * t1m + dk * om * om);
    float lad   = __logf(dnum) - 2.0f * __logf(den);

    yout   = inside ? y : xin;
    ladout = inside ? lad : 0.0f;
}

extern "C" __global__ void __launch_bounds__(THREADS, 1)
nsf_kernel(const float* __restrict__ x,
           const float* __restrict__ W_in,  const float* __restrict__ b_in,
           const float* __restrict__ W_blk, const float* __restrict__ b_blk,
           const float* __restrict__ W_out, const float* __restrict__ b_out,
           float* __restrict__ out, int n) {
    extern __shared__ float sm[];
    float* sWt  = sm + SM_WT;
    float* sWo  = sm + SM_WO;
    float* sWin = sm + SM_WIN;
    float* sbin = sm + SM_BIN;
    float* sbb  = sm + SM_BBLK;
    float* sbo  = sm + SM_BOUT;
    float* sh   = sm + SM_H;
    float* st   = sm + SM_T;

    const int tid = threadIdx.x;
    const int g0r = blockIdx.x * COLS + tid;          // column A point
    const int g1r = g0r + 128;                        // column B point
    const bool v0 = (g0r < n), v1 = (g1r < n);
    const int g0 = v0 ? g0r : (n - 1);
    const int g1 = v1 ? g1r : (n - 1);

    float az0 = x[3 * g0 + 0], az1 = x[3 * g0 + 1], az2 = x[3 * g0 + 2];
    float bz0 = x[3 * g1 + 0], bz1 = x[3 * g1 + 1], bz2 = x[3 * g1 + 2];
    float lad_a = 0.0f, lad_b = 0.0f;

    for (int it = 0; it < 8; ++it) {
        __syncthreads();   // previous transform done reading weights

        // ---- stage weights into smem (transposed, coalesced gmem reads) ----
        const float* gW = W_blk + it * 16384;
        for (int idx = tid; idx < 16384; idx += THREADS) {
            int l = idx >> 12, rem = idx & 4095, o = rem >> 6, k = rem & 63;
            sWt[(l * 64 + k) * PW + o] = gW[idx];
        }
        const float* gWo = W_out + it * 74 * 64;
        for (int idx = tid; idx < 74 * 64; idx += THREADS) {
            int o = idx >> 6, k = idx & 63;
            int col = (o < 37) ? o : (o + 3);
            sWo[k * PO + col] = gWo[idx];
        }
        if (tid < 64) {
            sWin[tid] = W_in[it * 64 + tid];
            sbin[tid] = b_in[it * 64 + tid];
        }
        for (int idx = tid; idx < 256; idx += THREADS)
            sbb[idx] = b_blk[it * 256 + idx];
        if (tid < 74) {
            int col = (tid < 37) ? tid : (tid + 3);
            sbo[col] = b_out[it * 74 + tid];
        }
        __syncthreads();

        // ---- reverse z; split ident/tr for both columns ----
        float ca = az2, ta0 = az1, ta1 = az0;
        float cb = bz2, tb0 = bz1, tb1 = bz0;

        // h = ident * W_in + b_in
#pragma unroll 8
        for (int o = 0; o < 64; ++o) {
            float w = sWin[o], b = sbin[o];
            sh[(o << 8) + tid]       = fmaf(ca, w, b);
            sh[(o << 8) + tid + 128] = fmaf(cb, w, b);
        }

        // two residual blocks
        dense64_p2<true, false>(sWt,            sbb,       sh, st, tid);
        dense64_p2<true, true >(sWt +  64 * PW, sbb +  64, st, sh, tid);
        dense64_p2<true, false>(sWt + 128 * PW, sbb + 128, sh, st, tid);
        dense64_p2<true, true >(sWt + 192 * PW, sbb + 192, st, sh, tid);

        // output params + splines, one (column, dim) at a time
        float ya0, la0, ya1, la1, yb0, lb0, yb1, lb1;
        {
            float p[37];
            denseOutHalf(sWo,      sbo,      sh, tid, p);
            rq_spline(p, ta0, ya0, la0);
        }
        {
            float p[37];
            denseOutHalf(sWo + 40, sbo + 40, sh, tid, p);
            rq_spline(p, ta1, ya1, la1);
        }
        {
            float p[37];
            denseOutHalf(sWo,      sbo,      sh, tid + 128, p);
            rq_spline(p, tb0, yb0, lb0);
        }
        {
            float p[37];
            denseOutHalf(sWo + 40, sbo + 40, sh, tid + 128, p);
            rq_spline(p, tb1, yb1, lb1);
        }

        az0 = ca; az1 = ya0; az2 = ya1;
        bz0 = cb; bz1 = yb0; bz2 = yb1;
        lad_a += la0 + la1;
        lad_b += lb0 + lb1;
    }

    if (v0)
        out[g0r] = fmaf(-0.5f, az0 * az0 + az1 * az1 + az2 * az2, LOGZc + lad_a);
    if (v1)
        out[g1r] = fmaf(-0.5f, bz0 * bz0 + bz1 * bz1 + bz2 * bz2, LOGZc + lad_b);
}

extern "C" void kernel_launch(void* const* d_in, const int* in_sizes, int n_in,
                              void* d_out, int out_size) {
    const float* x     = (const float*)d_in[0];
    const float* W_in  = (const float*)d_in[1];
    const float* b_in  = (const float*)d_in[2];
    const float* W_blk = (const float*)d_in[3];
    const float* b_blk = (const float*)d_in[4];
    const float* W_out = (const float*)d_in[5];
    const float* b_out = (const float*)d_in[6];
    float* out = (float*)d_out;

    int n = in_sizes[0] / 3;
    cudaFuncSetAttribute(nsf_kernel, cudaFuncAttributeMaxDynamicSharedMemorySize,
                         SMEM_BYTES);
    int blocks = (n + COLS - 1) / COLS;
    nsf_kernel<<<blocks, THREADS, SMEM_BYTES>>>(x, W_in, b_in, W_blk, b_blk,
                                                W_out, b_out, out, n);
}

// round 5
// speedup vs baseline: 1.3985x; 1.3985x over previous
#include <cuda_runtime.h>

// ---------------------------------------------------------------------------
// NeuralSplineFlow3D fused kernel — fp32 FFMA2, 2-D register tiling:
// CTA = 256 points x 64 outputs, thread = 4 points x 16 outputs.
// R5: fix sbo pad-zero index typo (71+pc -> 74+pc) that clobbered real biases.
// ---------------------------------------------------------------------------

#define THREADS   256
#define COLS      256
#define PW        68           // smem pitch (floats) for 64-wide hidden weights
#define PO        80           // smem pitch (floats) for output weights (2x37+pad)
#define TBc       5.0f
#define MINc      0.001f
#define LOGZc     (-2.7568155996140194f)   // -1.5*log(2*pi)
#define DCONSTf   (0.5397424697f)          // log(exp(1-0.001)-1)

// smem layout (float offsets)
#define SM_WT     0                         // 4*64*68 = 17408
#define SM_WO     (SM_WT + 4*64*PW)         // 64*80   = 5120
#define SM_WIN    (SM_WO + 64*PO)           // 64
#define SM_BIN    (SM_WIN + 64)             // 64
#define SM_BBLK   (SM_BIN + 64)             // 256
#define SM_BOUT   (SM_BBLK + 256)           // 80
#define SM_H      (SM_BOUT + PO)            // 64*256 = 16384
#define SM_T      (SM_H + 64*COLS)          // 64*256 = 16384
#define SM_TOTALF (SM_T + 64*COLS)
#define SMEM_BYTES (SM_TOTALF * 4)          // 223040 bytes

typedef unsigned long long u64;

static __device__ __forceinline__ u64 ffma2(u64 a, u64 b, u64 c) {
    u64 d;
    asm("fma.rn.f32x2 %0, %1, %2, %3;" : "=l"(d) : "l"(a), "l"(b), "l"(c));
    return d;
}
static __device__ __forceinline__ u64 pk2(float v) {
    u64 r;
    asm("mov.b64 %0, {%1, %1};" : "=l"(r) : "f"(v));
    return r;
}
static __device__ __forceinline__ void upk2(u64 v, float& lo, float& hi) {
    asm("mov.b64 {%0, %1}, %2;" : "=f"(lo), "=f"(hi) : "l"(v));
}
static __device__ __forceinline__ float softplusf(float x) {
    return fmaxf(x, 0.0f) + log1pf(__expf(-fabsf(x)));
}

// ---- residual dense layer, tiled: thread computes 4 pts x 16 outputs -------
template<bool ADD>
static __device__ __forceinline__ void dense_tile(const float* __restrict__ Wt,
                                                  const float* __restrict__ bias,
                                                  const float* __restrict__ inb,
                                                  float* __restrict__ dst,
                                                  int tx, int ty) {
    const int ob = 16 * ty;
    u64 acc[4][8];
#pragma unroll
    for (int q = 0; q < 8; ++q) {
        u64 b = *reinterpret_cast<const u64*>(bias + ob + 2 * q);
        acc[0][q] = b; acc[1][q] = b; acc[2][q] = b; acc[3][q] = b;
    }
    const float* cp = inb + 4 * tx;
#pragma unroll 1
    for (int k = 0; k < 64; ++k) {
        float4 a = *reinterpret_cast<const float4*>(cp + (k << 8));
        a.x = fmaxf(a.x, 0.0f); a.y = fmaxf(a.y, 0.0f);
        a.z = fmaxf(a.z, 0.0f); a.w = fmaxf(a.w, 0.0f);
        u64 r0 = pk2(a.x), r1 = pk2(a.y), r2 = pk2(a.z), r3 = pk2(a.w);
        const float* wr = Wt + k * PW + ob;
        ulonglong2 wA = *reinterpret_cast<const ulonglong2*>(wr);
        ulonglong2 wB = *reinterpret_cast<const ulonglong2*>(wr + 4);
        ulonglong2 wC = *reinterpret_cast<const ulonglong2*>(wr + 8);
        ulonglong2 wD = *reinterpret_cast<const ulonglong2*>(wr + 12);
        u64 w[8] = {wA.x, wA.y, wB.x, wB.y, wC.x, wC.y, wD.x, wD.y};
#pragma unroll
        for (int q = 0; q < 8; ++q) {
            acc[0][q] = ffma2(r0, w[q], acc[0][q]);
            acc[1][q] = ffma2(r1, w[q], acc[1][q]);
            acc[2][q] = ffma2(r2, w[q], acc[2][q]);
            acc[3][q] = ffma2(r3, w[q], acc[3][q]);
        }
    }
    // register transpose -> conflict-free STS.128 per output row
#pragma unroll
    for (int q = 0; q < 8; ++q) {
        float l0, h0, l1, h1, l2, h2, l3, h3;
        upk2(acc[0][q], l0, h0); upk2(acc[1][q], l1, h1);
        upk2(acc[2][q], l2, h2); upk2(acc[3][q], l3, h3);
        float4 vlo = make_float4(l0, l1, l2, l3);
        float4 vhi = make_float4(h0, h1, h2, h3);
        float* d0 = dst + ((ob + 2 * q) << 8) + 4 * tx;
        float* d1 = dst + ((ob + 2 * q + 1) << 8) + 4 * tx;
        if (ADD) {
            float4 e0 = *reinterpret_cast<const float4*>(d0);
            float4 e1 = *reinterpret_cast<const float4*>(d1);
            vlo.x += e0.x; vlo.y += e0.y; vlo.z += e0.z; vlo.w += e0.w;
            vhi.x += e1.x; vhi.y += e1.y; vhi.z += e1.z; vhi.w += e1.w;
        }
        *reinterpret_cast<float4*>(d0) = vlo;
        *reinterpret_cast<float4*>(d1) = vhi;
    }
}

extern "C" __global__ void __launch_bounds__(THREADS, 1)
nsf_kernel(const float* __restrict__ x,
           const float* __restrict__ W_in,  const float* __restrict__ b_in,
           const float* __restrict__ W_blk, const float* __restrict__ b_blk,
           const float* __restrict__ W_out, const float* __restrict__ b_out,
           float* __restrict__ out, int n) {
    extern __shared__ float sm[];
    float* sWt  = sm + SM_WT;
    float* sWo  = sm + SM_WO;
    float* sWin = sm + SM_WIN;
    float* sbin = sm + SM_BIN;
    float* sbb  = sm + SM_BBLK;
    float* sbo  = sm + SM_BOUT;
    float* sh   = sm + SM_H;
    float* st   = sm + SM_T;

    const int tid = threadIdx.x;
    const int tx  = tid & 63;
    const int ty  = tid >> 6;

    const int gidr = blockIdx.x * COLS + tid;
    const bool valid = (gidr < n);
    const int g = valid ? gidr : (n - 1);

    float z0 = x[3 * g + 0];
    float z1 = x[3 * g + 1];
    float z2 = x[3 * g + 2];
    float lad_total = 0.0f;

    for (int it = 0; it < 8; ++it) {
        __syncthreads();   // previous transform fully consumed weights + panels

        // ---- stage weights into smem (transposed, coalesced gmem reads) ----
        const float* gW = W_blk + it * 16384;
        for (int idx = tid; idx < 16384; idx += THREADS) {
            int l = idx >> 12, rem = idx & 4095, o = rem >> 6, k = rem & 63;
            sWt[(l * 64 + k) * PW + o] = gW[idx];
        }
        const float* gWo = W_out + it * 74 * 64;
        for (int idx = tid; idx < 74 * 64; idx += THREADS) {
            int o = idx >> 6, k = idx & 63;
            int col = (o < 37) ? o : (o + 3);
            sWo[k * PO + col] = gWo[idx];
        }
        // zero the 6 pad cols {37,38,39,77,78,79} of sWo
        for (int idx = tid; idx < 6 * 64; idx += THREADS) {
            int pc = idx % 6, k = idx / 6;
            int col = (pc < 3) ? (37 + pc) : (74 + pc);
            sWo[k * PO + col] = 0.0f;
        }
        if (tid < 64) {
            sWin[tid] = W_in[it * 64 + tid];
            sbin[tid] = b_in[it * 64 + tid];
        }
        sbb[tid] = b_blk[it * 256 + tid];
        if (tid < 74) {
            int col = (tid < 37) ? tid : (tid + 3);
            sbo[col] = b_out[it * 74 + tid];
        }
        if (tid >= 74 && tid < 80) {
            int pc = tid - 74;
            int col = (pc < 3) ? (37 + pc) : (74 + pc);   // pads {37,38,39,77,78,79}
            sbo[col] = 0.0f;
        }
        __syncthreads();

        // ---- reverse z; split ident/tr (per thread owns column tid) ----
        float c = z2, t0 = z1, t1 = z0;

        // h = ident * W_in + b_in   (thread writes its own column)
#pragma unroll 8
        for (int o = 0; o < 64; ++o)
            sh[(o << 8) + tid] = fmaf(c, sWin[o], sbin[o]);
        __syncthreads();

        // ---- two residual blocks ----
        dense_tile<false>(sWt,            sbb,       sh, st, tx, ty); __syncthreads();
        dense_tile<true >(sWt +  64 * PW, sbb +  64, st, sh, tx, ty); __syncthreads();
        dense_tile<false>(sWt + 128 * PW, sbb + 128, sh, st, tx, ty); __syncthreads();
        dense_tile<true >(sWt + 192 * PW, sbb + 192, st, sh, tx, ty); __syncthreads();

        // ---- output layer: thread computes 4 pts x 20 param-cols ----
        {
            const int ob = 20 * ty;           // slice of padded-80 param space
            u64 acc[4][10];
#pragma unroll
            for (int q = 0; q < 10; ++q) {
                u64 b = *reinterpret_cast<const u64*>(sbo + ob + 2 * q);
                acc[0][q] = b; acc[1][q] = b; acc[2][q] = b; acc[3][q] = b;
            }
            const float* cp = sh + 4 * tx;
#pragma unroll 1
            for (int k = 0; k < 64; ++k) {
                float4 a = *reinterpret_cast<const float4*>(cp + (k << 8));
                u64 r0 = pk2(a.x), r1 = pk2(a.y), r2 = pk2(a.z), r3 = pk2(a.w);
                const float* wr = sWo + k * PO + ob;
                ulonglong2 wA = *reinterpret_cast<const ulonglong2*>(wr);
                ulonglong2 wB = *reinterpret_cast<const ulonglong2*>(wr + 4);
                ulonglong2 wC = *reinterpret_cast<const ulonglong2*>(wr + 8);
                ulonglong2 wD = *reinterpret_cast<const ulonglong2*>(wr + 12);
                ulonglong2 wE = *reinterpret_cast<const ulonglong2*>(wr + 16);
                u64 w[10] = {wA.x, wA.y, wB.x, wB.y, wC.x, wC.y, wD.x, wD.y, wE.x, wE.y};
#pragma unroll
                for (int q = 0; q < 10; ++q) {
                    acc[0][q] = ffma2(r0, w[q], acc[0][q]);
                    acc[1][q] = ffma2(r1, w[q], acc[1][q]);
                    acc[2][q] = ffma2(r2, w[q], acc[2][q]);
                    acc[3][q] = ffma2(r3, w[q], acc[3][q]);
                }
            }
            __syncthreads();   // all reads of sh done before scatter writes sh rows

            // scatter params: padded row r -> st rows 0..63, sh rows 0..15
#pragma unroll
            for (int q = 0; q < 10; ++q) {
                float l0, h0, l1, h1, l2, h2, l3, h3;
                upk2(acc[0][q], l0, h0); upk2(acc[1][q], l1, h1);
                upk2(acc[2][q], l2, h2); upk2(acc[3][q], l3, h3);
                float4 vlo = make_float4(l0, l1, l2, l3);
                float4 vhi = make_float4(h0, h1, h2, h3);
                int r0 = ob + 2 * q, r1 = r0 + 1;
                float* p0 = (r0 < 64 ? st + (r0 << 8) : sh + ((r0 - 64) << 8)) + 4 * tx;
                float* p1 = (r1 < 64 ? st + (r1 << 8) : sh + ((r1 - 64) << 8)) + 4 * tx;
                *reinterpret_cast<float4*>(p0) = vlo;
                *reinterpret_cast<float4*>(p1) = vhi;
            }
        }
        __syncthreads();

        // ---- gather own point's params and run splines (column = tid) ----
        float y0, l0, y1, l1;
        {
            float p[37];
#pragma unroll
            for (int r = 0; r < 37; ++r) p[r] = st[(r << 8) + tid];
            {
                bool inside = (t0 >= -TBc) && (t0 <= TBc);
                float xc = fminf(fmaxf(t0, -TBc), TBc);
                int bin = 0;
                float in_cw, in_w, in_ch, in_h;
                {
                    float e[12]; float m = p[0];
#pragma unroll
                    for (int j = 1; j < 12; ++j) m = fmaxf(m, p[j]);
                    float s = 0.0f;
#pragma unroll
                    for (int j = 0; j < 12; ++j) { e[j] = __expf(p[j] - m); s += e[j]; }
                    float ci = 0.988f * __fdividef(1.0f, s);
#pragma unroll
                    for (int j = 0; j < 12; ++j) e[j] = fmaf(e[j], ci, MINc);
                    float run = 0.0f;
#pragma unroll
                    for (int j = 0; j < 12; ++j) {
                        run += e[j];
                        float ks = (j == 11) ? (TBc + 1e-6f) : fmaf(10.0f, run, -TBc);
                        if (xc >= ks) ++bin;
                    }
                    run = 0.0f; float prev = -TBc;
#pragma unroll
                    for (int j = 0; j < 12; ++j) {
                        run += e[j];
                        float right = (j == 11) ? TBc : fmaf(10.0f, run, -TBc);
                        if (j == bin) { in_cw = prev; in_w = right - prev; }
                        prev = right;
                    }
                }
                {
                    float e[12]; float m = p[12];
#pragma unroll
                    for (int j = 1; j < 12; ++j) m = fmaxf(m, p[12 + j]);
                    float s = 0.0f;
#pragma unroll
                    for (int j = 0; j < 12; ++j) { e[j] = __expf(p[12 + j] - m); s += e[j]; }
                    float ci = 0.988f * __fdividef(1.0f, s);
#pragma unroll
                    for (int j = 0; j < 12; ++j) e[j] = fmaf(e[j], ci, MINc);
                    float run = 0.0f; float prev = -TBc;
#pragma unroll
                    for (int j = 0; j < 12; ++j) {
                        run += e[j];
                        float right = (j == 11) ? TBc : fmaf(10.0f, run, -TBc);
                        if (j == bin) { in_ch = prev; in_h = right - prev; }
                        prev = right;
                    }
                }
                float uk = DCONSTf, uk1 = DCONSTf;
#pragma unroll
                for (int j = 1; j <= 12; ++j) {
                    float v = p[23 + j];
                    if (j == bin)     uk  = v;
                    if (j == bin + 1) uk1 = v;
                }
                float dk  = MINc + softplusf(uk);
                float dk1 = MINc + softplusf(uk1);
                float invw  = __fdividef(1.0f, in_w);
                float delta = in_h * invw;
                float theta = (xc - in_cw) * invw;
                float om    = 1.0f - theta;
                float t1m   = theta * om;
                float th2   = theta * theta;
                float num   = in_h * (delta * th2 + dk * t1m);
                float den   = delta + (dk + dk1 - 2.0f * delta) * t1m;
                float yv    = in_ch + __fdividef(num, den);
                float dnum  = (delta * delta) * (dk1 * th2 + 2.0f * delta * t1m + dk * om * om);
                float lad   = __logf(dnum) - 2.0f * __logf(den);
                y0 = inside ? yv : t0;
                l0 = inside ? lad : 0.0f;
            }
        }
        {
            float p[37];
#pragma unroll
            for (int r = 40; r < 64; ++r) p[r - 40] = st[(r << 8) + tid];
#pragma unroll
            for (int r = 64; r < 77; ++r) p[r - 40] = sh[((r - 64) << 8) + tid];
            {
                bool inside = (t1 >= -TBc) && (t1 <= TBc);
                float xc = fminf(fmaxf(t1, -TBc), TBc);
                int bin = 0;
                float in_cw, in_w, in_ch, in_h;
                {
                    float e[12]; float m = p[0];
#pragma unroll
                    for (int j = 1; j < 12; ++j) m = fmaxf(m, p[j]);
                    float s = 0.0f;
#pragma unroll
                    for (int j = 0; j < 12; ++j) { e[j] = __expf(p[j] - m); s += e[j]; }
                    float ci = 0.988f * __fdividef(1.0f, s);
#pragma unroll
                    for (int j = 0; j < 12; ++j) e[j] = fmaf(e[j], ci, MINc);
                    float run = 0.0f;
#pragma unroll
                    for (int j = 0; j < 12; ++j) {
                        run += e[j];
                        float ks = (j == 11) ? (TBc + 1e-6f) : fmaf(10.0f, run, -TBc);
                        if (xc >= ks) ++bin;
                    }
                    run = 0.0f; float prev = -TBc;
#pragma unroll
                    for (int j = 0; j < 12; ++j) {
                        run += e[j];
                        float right = (j == 11) ? TBc : fmaf(10.0f, run, -TBc);
                        if (j == bin) { in_cw = prev; in_w = right - prev; }
                        prev = right;
                    }
                }
                {
                    float e[12]; float m = p[12];
#pragma unroll
                    for (int j = 1; j < 12; ++j) m = fmaxf(m, p[12 + j]);
                    float s = 0.0f;
#pragma unroll
                    for (int j = 0; j < 12; ++j) { e[j] = __expf(p[12 + j] - m); s += e[j]; }
                    float ci = 0.988f * __fdividef(1.0f, s);
#pragma unroll
                    for (int j = 0; j < 12; ++j) e[j] = fmaf(e[j], ci, MINc);
                    float run = 0.0f; float prev = -TBc;
#pragma unroll
                    for (int j = 0; j < 12; ++j) {
                        run += e[j];
                        float right = (j == 11) ? TBc : fmaf(10.0f, run, -TBc);
                        if (j == bin) { in_ch = prev; in_h = right - prev; }
                        prev = right;
                    }
                }
                float uk = DCONSTf, uk1 = DCONSTf;
#pragma unroll
                for (int j = 1; j <= 12; ++j) {
                    float v = p[23 + j];
                    if (j == bin)     uk  = v;
                    if (j == bin + 1) uk1 = v;
                }
                float dk  = MINc + softplusf(uk);
                float dk1 = MINc + softplusf(uk1);
                float invw  = __fdividef(1.0f, in_w);
                float delta = in_h * invw;
                float theta = (xc - in_cw) * invw;
                float om    = 1.0f - theta;
                float t1m   = theta * om;
                float th2   = theta * theta;
                float num   = in_h * (delta * th2 + dk * t1m);
                float den   = delta + (dk + dk1 - 2.0f * delta) * t1m;
                float yv    = in_ch + __fdividef(num, den);
                float dnum  = (delta * delta) * (dk1 * th2 + 2.0f * delta * t1m + dk * om * om);
                float lad   = __logf(dnum) - 2.0f * __logf(den);
                y1 = inside ? yv : t1;
                l1 = inside ? lad : 0.0f;
            }
        }

        z0 = c; z1 = y0; z2 = y1;
        lad_total += l0 + l1;
    }

    if (valid)
        out[gidr] = fmaf(-0.5f, z0 * z0 + z1 * z1 + z2 * z2, LOGZc + lad_total);
}

extern "C" void kernel_launch(void* const* d_in, const int* in_sizes, int n_in,
                              void* d_out, int out_size) {
    const float* x     = (const float*)d_in[0];
    const float* W_in  = (const float*)d_in[1];
    const float* b_in  = (const float*)d_in[2];
    const float* W_blk = (const float*)d_in[3];
    const float* b_blk = (const float*)d_in[4];
    const float* W_out = (const float*)d_in[5];
    const float* b_out = (const float*)d_in[6];
    float* out = (float*)d_out;

    int n = in_sizes[0] / 3;
    cudaFuncSetAttribute(nsf_kernel, cudaFuncAttributeMaxDynamicSharedMemorySize,
                         SMEM_BYTES);
    int blocks = (n + COLS - 1) / COLS;
    nsf_kernel<<<blocks, THREADS, SMEM_BYTES>>>(x, W_in, b_in, W_blk, b_blk,
                                                W_out, b_out, out, n);
}

// round 6
// speedup vs baseline: 1.7285x; 1.2359x over previous
#include <cuda_runtime.h>

// ---------------------------------------------------------------------------
// NeuralSplineFlow3D fused kernel — fp32 FFMA2, point-pair accumulators,
// duplicated weights in smem (LDS.128 -> FFMA2 directly, no MOVs).
// CTA = 256 points x 64 outputs, thread = 4 points x 16 outputs.
// ---------------------------------------------------------------------------

#define THREADS   256
#define COLS      256
#define PWD       132          // dup hidden-weight pitch (floats), 16B aligned
#define POD       164          // dup out-weight pitch (floats), 16B aligned
#define TBc       5.0f
#define MINc      0.001f
#define LOGZc     (-2.7568155996140194f)   // -1.5*log(2*pi)
#define DCONSTf   (0.5397424697f)          // log(exp(1-0.001)-1)

// smem layout (float offsets)
#define SM_DUP    0                          // 2*64*132 = 16896 (also out dup 64*164=10496)
#define SM_H      16896                      // 64*256 = 16384
#define SM_T      (SM_H + 16384)             // 64*256 = 16384
#define SM_WIN    (SM_T + 16384)             // 64
#define SM_BIN    (SM_WIN + 64)              // 64
#define SM_BBD    (SM_BIN + 64)              // 512 (4 layers x 128 dup bias)
#define SM_BOD    (SM_BBD + 512)             // 160 (dup out bias, padded)
#define SM_TOTALF (SM_BOD + 160)
#define SMEM_BYTES (SM_TOTALF * 4)           // 201856 bytes

typedef unsigned long long u64;

static __device__ __forceinline__ u64 ffma2(u64 a, u64 b, u64 c) {
    u64 d;
    asm("fma.rn.f32x2 %0, %1, %2, %3;" : "=l"(d) : "l"(a), "l"(b), "l"(c));
    return d;
}
static __device__ __forceinline__ u64 add2(u64 a, u64 b) {
    u64 d;
    asm("add.rn.f32x2 %0, %1, %2;" : "=l"(d) : "l"(a), "l"(b));
    return d;
}
static __device__ __forceinline__ u64 pkxy(float x, float y) {
    u64 r;
    asm("mov.b64 %0, {%1, %2};" : "=l"(r) : "f"(x), "f"(y));
    return r;
}
static __device__ __forceinline__ u64 pk2(float v) {
    u64 r;
    asm("mov.b64 %0, {%1, %1};" : "=l"(r) : "f"(v));
    return r;
}
static __device__ __forceinline__ float softplusf(float x) {
    return fmaxf(x, 0.0f) + log1pf(__expf(-fabsf(x)));
}

// ---- hidden dense layer: thread = 4 pts x 16 outs, dup weights -------------
// Wd: dup layout [k][2*o], pitch PWD. biasd: dup bias (128 floats).
template<bool ADD>
static __device__ __forceinline__ void dense_tile(const float* __restrict__ Wd,
                                                  const float* __restrict__ biasd,
                                                  const float* __restrict__ inb,
                                                  float* __restrict__ dst,
                                                  int tx, int ty) {
    const int ob = 16 * ty;
    u64 a01[16], a23[16];
#pragma unroll
    for (int q = 0; q < 16; ++q) {
        u64 b = *reinterpret_cast<const u64*>(biasd + 2 * (ob + q));
        a01[q] = b; a23[q] = b;
    }
    const float* cp = inb + 4 * tx;
    const float* wp = Wd + 2 * ob;
#pragma unroll 2
    for (int k = 0; k < 64; ++k) {
        float4 a = *reinterpret_cast<const float4*>(cp + (k << 8));
        u64 r01 = pkxy(fmaxf(a.x, 0.0f), fmaxf(a.y, 0.0f));
        u64 r23 = pkxy(fmaxf(a.z, 0.0f), fmaxf(a.w, 0.0f));
        const float* wr = wp + k * PWD;
#pragma unroll
        for (int q = 0; q < 8; ++q) {
            ulonglong2 w = *reinterpret_cast<const ulonglong2*>(wr + 4 * q);
            a01[2 * q]     = ffma2(r01, w.x, a01[2 * q]);
            a23[2 * q]     = ffma2(r23, w.x, a23[2 * q]);
            a01[2 * q + 1] = ffma2(r01, w.y, a01[2 * q + 1]);
            a23[2 * q + 1] = ffma2(r23, w.y, a23[2 * q + 1]);
        }
    }
#pragma unroll
    for (int q = 0; q < 16; ++q) {
        float* d = dst + ((ob + q) << 8) + 4 * tx;
        ulonglong2 v;
        if (ADD) {
            ulonglong2 e = *reinterpret_cast<const ulonglong2*>(d);
            v.x = add2(a01[q], e.x);
            v.y = add2(a23[q], e.y);
        } else {
            v.x = a01[q];
            v.y = a23[q];
        }
        *reinterpret_cast<ulonglong2*>(d) = v;
    }
}

extern "C" __global__ void __launch_bounds__(THREADS, 1)
nsf_kernel(const float* __restrict__ x,
           const float* __restrict__ W_in,  const float* __restrict__ b_in,
           const float* __restrict__ W_blk, const float* __restrict__ b_blk,
           const float* __restrict__ W_out, const float* __restrict__ b_out,
           float* __restrict__ out, int n) {
    extern __shared__ float sm[];
    float* sDup = sm + SM_DUP;
    float* sh   = sm + SM_H;
    float* st   = sm + SM_T;
    float* sWin = sm + SM_WIN;
    float* sbin = sm + SM_BIN;
    float* sBBD = sm + SM_BBD;
    float* sBOD = sm + SM_BOD;

    const int tid = threadIdx.x;
    const int tx  = tid & 63;
    const int ty  = tid >> 6;

    const int gidr = blockIdx.x * COLS + tid;
    const bool valid = (gidr < n);
    const int g = valid ? gidr : (n - 1);

    float z0 = x[3 * g + 0];
    float z1 = x[3 * g + 1];
    float z2 = x[3 * g + 2];
    float lad_total = 0.0f;

    for (int it = 0; it < 8; ++it) {
        __syncthreads();   // previous transform fully done with panels/weights

        // ---- small staging: W_in, b_in, dup block biases, dup out biases ----
        if (tid < 64) {
            sWin[tid] = W_in[it * 64 + tid];
            sbin[tid] = b_in[it * 64 + tid];
        }
        {   // dup biases: sBBD[l*128 + 2o] = b_blk[it, l, o] (both halves)
            float v = b_blk[it * 256 + tid];          // tid = l*64+o
            int l = tid >> 6, o = tid & 63;
            float* d = sBBD + l * 128 + 2 * o;
            d[0] = v; d[1] = v;
        }
        if (tid < 74) {
            int p = (tid < 37) ? tid : (tid + 3);
            float v = b_out[it * 74 + tid];
            sBOD[2 * p] = v; sBOD[2 * p + 1] = v;
        } else if (tid < 80) {
            int pc = tid - 74;
            int p = (pc < 3) ? (37 + pc) : (74 + pc);  // pads {37,38,39,77,78,79}
            sBOD[2 * p] = 0.0f; sBOD[2 * p + 1] = 0.0f;
        }

        // ---- stage hidden layers 0,1 duplicated ----
        {
            const float* gW = W_blk + it * 16384;     // layers 0,1 = first 8192
            for (int idx = tid; idx < 4096; idx += THREADS) {
                int kq = idx & 31;                    // k pair
                int o  = (idx >> 5) & 63;
                int l  = idx >> 11;                   // 0,1
                float2 w = *reinterpret_cast<const float2*>(gW + (l * 64 + o) * 64 + 2 * kq);
                float* b = sDup + (l * 64 + 2 * kq) * PWD + 2 * o;
                *reinterpret_cast<u64*>(b)       = pk2(w.x);
                *reinterpret_cast<u64*>(b + PWD) = pk2(w.y);
            }
        }
        __syncthreads();

        // ---- reverse z; split ident/tr ----
        float c = z2, t0 = z1, t1 = z0;

        // h = ident * W_in + b_in
#pragma unroll 8
        for (int o = 0; o < 64; ++o)
            sh[(o << 8) + tid] = fmaf(c, sWin[o], sbin[o]);
        __syncthreads();

        // ---- residual block 1 ----
        dense_tile<false>(sDup,            sBBD,       sh, st, tx, ty); __syncthreads();
        dense_tile<true >(sDup + 64 * PWD, sBBD + 128, st, sh, tx, ty); __syncthreads();

        // ---- stage hidden layers 2,3 duplicated (st/sDup dead here) ----
        {
            const float* gW = W_blk + it * 16384 + 8192;
            for (int idx = tid; idx < 4096; idx += THREADS) {
                int kq = idx & 31;
                int o  = (idx >> 5) & 63;
                int l  = idx >> 11;
                float2 w = *reinterpret_cast<const float2*>(gW + (l * 64 + o) * 64 + 2 * kq);
                float* b = sDup + (l * 64 + 2 * kq) * PWD + 2 * o;
                *reinterpret_cast<u64*>(b)       = pk2(w.x);
                *reinterpret_cast<u64*>(b + PWD) = pk2(w.y);
            }
        }
        __syncthreads();

        // ---- residual block 2 ----
        dense_tile<false>(sDup,            sBBD + 256, sh, st, tx, ty); __syncthreads();
        dense_tile<true >(sDup + 64 * PWD, sBBD + 384, st, sh, tx, ty); __syncthreads();

        // ---- stage out weights duplicated into sDup (hidden weights dead) ----
        {
            const float* gWo = W_out + it * 74 * 64;
            for (int idx = tid; idx < 74 * 32; idx += THREADS) {
                int kq = idx & 31;
                int o  = idx >> 5;                    // 0..73
                float2 w = *reinterpret_cast<const float2*>(gWo + o * 64 + 2 * kq);
                int p = (o < 37) ? o : (o + 3);
                float* b = sDup + (2 * kq) * POD + 2 * p;
                *reinterpret_cast<u64*>(b)       = pk2(w.x);
                *reinterpret_cast<u64*>(b + POD) = pk2(w.y);
            }
            // zero pads p in {37,38,39,77,78,79}
            for (int idx = tid; idx < 6 * 64; idx += THREADS) {
                int pc = idx % 6, k = idx / 6;
                int p = (pc < 3) ? (37 + pc) : (74 + pc);
                *reinterpret_cast<u64*>(sDup + k * POD + 2 * p) = 0ull;
            }
        }
        __syncthreads();

        // ---- output layer: thread = 4 pts x 20 param cols ----
        {
            const int ob = 20 * ty;
            u64 a01[20], a23[20];
#pragma unroll
            for (int q = 0; q < 20; ++q) {
                u64 b = *reinterpret_cast<const u64*>(sBOD + 2 * (ob + q));
                a01[q] = b; a23[q] = b;
            }
            const float* cp = sh + 4 * tx;
            const float* wp = sDup + 2 * ob;
#pragma unroll 2
            for (int k = 0; k < 64; ++k) {
                float4 a = *reinterpret_cast<const float4*>(cp + (k << 8));
                u64 r01 = pkxy(a.x, a.y);
                u64 r23 = pkxy(a.z, a.w);
                const float* wr = wp + k * POD;
#pragma unroll
                for (int q = 0; q < 10; ++q) {
                    ulonglong2 w = *reinterpret_cast<const ulonglong2*>(wr + 4 * q);
                    a01[2 * q]     = ffma2(r01, w.x, a01[2 * q]);
                    a23[2 * q]     = ffma2(r23, w.x, a23[2 * q]);
                    a01[2 * q + 1] = ffma2(r01, w.y, a01[2 * q + 1]);
                    a23[2 * q + 1] = ffma2(r23, w.y, a23[2 * q + 1]);
                }
            }
            __syncthreads();   // all reads of sh done before scatter writes sh rows

            // scatter params: padded row r -> st rows 0..63, sh rows 0..15
#pragma unroll
            for (int q = 0; q < 20; ++q) {
                int r = ob + q;
                float* p = (r < 64 ? st + (r << 8) : sh + ((r - 64) << 8)) + 4 * tx;
                ulonglong2 v; v.x = a01[q]; v.y = a23[q];
                *reinterpret_cast<ulonglong2*>(p) = v;
            }
        }
        __syncthreads();

        // ---- gather own point's params and run splines (column = tid) ----
        float y0, l0, y1, l1;
        {
            float p[37];
#pragma unroll
            for (int r = 0; r < 37; ++r) p[r] = st[(r << 8) + tid];
            {
                bool inside = (t0 >= -TBc) && (t0 <= TBc);
                float xc = fminf(fmaxf(t0, -TBc), TBc);
                int bin = 0;
                float in_cw, in_w, in_ch, in_h;
                {
                    float e[12]; float m = p[0];
#pragma unroll
                    for (int j = 1; j < 12; ++j) m = fmaxf(m, p[j]);
                    float s = 0.0f;
#pragma unroll
                    for (int j = 0; j < 12; ++j) { e[j] = __expf(p[j] - m); s += e[j]; }
                    float ci = 0.988f * __fdividef(1.0f, s);
#pragma unroll
                    for (int j = 0; j < 12; ++j) e[j] = fmaf(e[j], ci, MINc);
                    float run = 0.0f;
#pragma unroll
                    for (int j = 0; j < 12; ++j) {
                        run += e[j];
                        float ks = (j == 11) ? (TBc + 1e-6f) : fmaf(10.0f, run, -TBc);
                        if (xc >= ks) ++bin;
                    }
                    run = 0.0f; float prev = -TBc;
#pragma unroll
                    for (int j = 0; j < 12; ++j) {
                        run += e[j];
                        float right = (j == 11) ? TBc : fmaf(10.0f, run, -TBc);
                        if (j == bin) { in_cw = prev; in_w = right - prev; }
                        prev = right;
                    }
                }
                {
                    float e[12]; float m = p[12];
#pragma unroll
                    for (int j = 1; j < 12; ++j) m = fmaxf(m, p[12 + j]);
                    float s = 0.0f;
#pragma unroll
                    for (int j = 0; j < 12; ++j) { e[j] = __expf(p[12 + j] - m); s += e[j]; }
                    float ci = 0.988f * __fdividef(1.0f, s);
#pragma unroll
                    for (int j = 0; j < 12; ++j) e[j] = fmaf(e[j], ci, MINc);
                    float run = 0.0f; float prev = -TBc;
#pragma unroll
                    for (int j = 0; j < 12; ++j) {
                        run += e[j];
                        float right = (j == 11) ? TBc : fmaf(10.0f, run, -TBc);
                        if (j == bin) { in_ch = prev; in_h = right - prev; }
                        prev = right;
                    }
                }
                float uk = DCONSTf, uk1 = DCONSTf;
#pragma unroll
                for (int j = 1; j <= 12; ++j) {
                    float v = p[23 + j];
                    if (j == bin)     uk  = v;
                    if (j == bin + 1) uk1 = v;
                }
                float dk  = MINc + softplusf(uk);
                float dk1 = MINc + softplusf(uk1);
                float invw  = __fdividef(1.0f, in_w);
                float delta = in_h * invw;
                float theta = (xc - in_cw) * invw;
                float om    = 1.0f - theta;
                float t1m   = theta * om;
                float th2   = theta * theta;
                float num   = in_h * (delta * th2 + dk * t1m);
                float den   = delta + (dk + dk1 - 2.0f * delta) * t1m;
                float yv    = in_ch + __fdividef(num, den);
                float dnum  = (delta * delta) * (dk1 * th2 + 2.0f * delta * t1m + dk * om * om);
                float lad   = __logf(dnum) - 2.0f * __logf(den);
                y0 = inside ? yv : t0;
                l0 = inside ? lad : 0.0f;
            }
        }
        {
            float p[37];
#pragma unroll
            for (int r = 40; r < 64; ++r) p[r - 40] = st[(r << 8) + tid];
#pragma unroll
            for (int r = 64; r < 77; ++r) p[r - 40] = sh[((r - 64) << 8) + tid];
            {
                bool inside = (t1 >= -TBc) && (t1 <= TBc);
                float xc = fminf(fmaxf(t1, -TBc), TBc);
                int bin = 0;
                float in_cw, in_w, in_ch, in_h;
                {
                    float e[12]; float m = p[0];
#pragma unroll
                    for (int j = 1; j < 12; ++j) m = fmaxf(m, p[j]);
                    float s = 0.0f;
#pragma unroll
                    for (int j = 0; j < 12; ++j) { e[j] = __expf(p[j] - m); s += e[j]; }
                    float ci = 0.988f * __fdividef(1.0f, s);
#pragma unroll
                    for (int j = 0; j < 12; ++j) e[j] = fmaf(e[j], ci, MINc);
                    float run = 0.0f;
#pragma unroll
                    for (int j = 0; j < 12; ++j) {
                        run += e[j];
                        float ks = (j == 11) ? (TBc + 1e-6f) : fmaf(10.0f, run, -TBc);
                        if (xc >= ks) ++bin;
                    }
                    run = 0.0f; float prev = -TBc;
#pragma unroll
                    for (int j = 0; j < 12; ++j) {
                        run += e[j];
                        float right = (j == 11) ? TBc : fmaf(10.0f, run, -TBc);
                        if (j == bin) { in_cw = prev; in_w = right - prev; }
                        prev = right;
                    }
                }
                {
                    float e[12]; float m = p[12];
#pragma unroll
                    for (int j = 1; j < 12; ++j) m = fmaxf(m, p[12 + j]);
                    float s = 0.0f;
#pragma unroll
                    for (int j = 0; j < 12; ++j) { e[j] = __expf(p[12 + j] - m); s += e[j]; }
                    float ci = 0.988f * __fdividef(1.0f, s);
#pragma unroll
                    for (int j = 0; j < 12; ++j) e[j] = fmaf(e[j], ci, MINc);
                    float run = 0.0f; float prev = -TBc;
#pragma unroll
                    for (int j = 0; j < 12; ++j) {
                        run += e[j];
                        float right = (j == 11) ? TBc : fmaf(10.0f, run, -TBc);
                        if (j == bin) { in_ch = prev; in_h = right - prev; }
                        prev = right;
                    }
                }
                float uk = DCONSTf, uk1 = DCONSTf;
#pragma unroll
                for (int j = 1; j <= 12; ++j) {
                    float v = p[23 + j];
                    if (j == bin)     uk  = v;
                    if (j == bin + 1) uk1 = v;
                }
                float dk  = MINc + softplusf(uk);
                float dk1 = MINc + softplusf(uk1);
                float invw  = __fdividef(1.0f, in_w);
                float delta = in_h * invw;
                float theta = (xc - in_cw) * invw;
                float om    = 1.0f - theta;
                float t1m   = theta * om;
                float th2   = theta * theta;
                float num   = in_h * (delta * th2 + dk * t1m);
                float den   = delta + (dk + dk1 - 2.0f * delta) * t1m;
                float yv    = in_ch + __fdividef(num, den);
                float dnum  = (delta * delta) * (dk1 * th2 + 2.0f * delta * t1m + dk * om * om);
                float lad   = __logf(dnum) - 2.0f * __logf(den);
                y1 = inside ? yv : t1;
                l1 = inside ? lad : 0.0f;
            }
        }

        z0 = c; z1 = y0; z2 = y1;
        lad_total += l0 + l1;
    }

    if (valid)
        out[gidr] = fmaf(-0.5f, z0 * z0 + z1 * z1 + z2 * z2, LOGZc + lad_total);
}

extern "C" void kernel_launch(void* const* d_in, const int* in_sizes, int n_in,
                              void* d_out, int out_size) {
    const float* x     = (const float*)d_in[0];
    const float* W_in  = (const float*)d_in[1];
    const float* b_in  = (const float*)d_in[2];
    const float* W_blk = (const float*)d_in[3];
    const float* b_blk = (const float*)d_in[4];
    const float* W_out = (const float*)d_in[5];
    const float* b_out = (const float*)d_in[6];
    float* out = (float*)d_out;

    int n = in_sizes[0] / 3;
    cudaFuncSetAttribute(nsf_kernel, cudaFuncAttributeMaxDynamicSharedMemorySize,
                         SMEM_BYTES);
    int blocks = (n + COLS - 1) / COLS;
    nsf_kernel<<<blocks, THREADS, SMEM_BYTES>>>(x, W_in, b_in, W_blk, b_blk,
                                                W_out, b_out, out, n);
}

// round 8
// speedup vs baseline: 1.8471x; 1.0686x over previous
#include <cuda_runtime.h>

// ---------------------------------------------------------------------------
// NeuralSplineFlow3D fused kernel — fp32 FFMA2, output-pair accumulators,
// non-dup weights used directly from LDS.128 (.x/.y), single staging pass.
// CTA = 256 points x 64 outputs, thread = 4 points x 16 outputs.
// ---------------------------------------------------------------------------

#define THREADS   256
#define COLS      256
#define PW        68           // smem pitch (floats) for 64-wide hidden weights
#define PO        80           // smem pitch (floats) for output weights (2x37+pad)
#define TBc       5.0f
#define MINc      0.001f
#define LOGZc     (-2.7568155996140194f)   // -1.5*log(2*pi)
#define DCONSTf   (0.5397424697f)          // log(exp(1-0.001)-1)

// smem layout (float offsets) — same as R2 (223040 B, known to fit)
#define SM_WT     0                         // 4*64*68 = 17408
#define SM_WO     (SM_WT + 4*64*PW)         // 64*80   = 5120
#define SM_WIN    (SM_WO + 64*PO)           // 64
#define SM_BIN    (SM_WIN + 64)             // 64
#define SM_BBLK   (SM_BIN + 64)             // 256
#define SM_BOUT   (SM_BBLK + 256)           // 80
#define SM_H      (SM_BOUT + PO)            // 64*256 = 16384
#define SM_T      (SM_H + 64*COLS)          // 64*256 = 16384
#define SM_TOTALF (SM_T + 64*COLS)
#define SMEM_BYTES (SM_TOTALF * 4)          // 223040 bytes

typedef unsigned long long u64;

static __device__ __forceinline__ u64 ffma2(u64 a, u64 b, u64 c) {
    u64 d;
    asm("fma.rn.f32x2 %0, %1, %2, %3;" : "=l"(d) : "l"(a), "l"(b), "l"(c));
    return d;
}
static __device__ __forceinline__ u64 pk2(float v) {
    u64 r;
    asm("mov.b64 %0, {%1, %1};" : "=l"(r) : "f"(v));
    return r;
}
static __device__ __forceinline__ void upk2(u64 v, float& lo, float& hi) {
    asm("mov.b64 {%0, %1}, %2;" : "=f"(lo), "=f"(hi) : "l"(v));
}
static __device__ __forceinline__ float softplusf(float x) {
    return fmaxf(x, 0.0f) + log1pf(__expf(-fabsf(x)));
}

// ---- hidden dense layer: thread = 4 pts x 16 outs, non-dup weights ---------
// acc[p][q] packs outputs (ob+2q, ob+2q+1) for point p. Weights used directly
// from ulonglong2 components (no intermediate array -> no MOVs).
template<bool ADD>
static __device__ __forceinline__ void dense_tile(const float* __restrict__ Wt,
                                                  const float* __restrict__ bias,
                                                  const float* __restrict__ inb,
                                                  float* __restrict__ dst,
                                                  int tx, int ty) {
    const int ob = 16 * ty;
    u64 acc[4][8];
#pragma unroll
    for (int q = 0; q < 8; ++q) {
        u64 b = *reinterpret_cast<const u64*>(bias + ob + 2 * q);
        acc[0][q] = b; acc[1][q] = b; acc[2][q] = b; acc[3][q] = b;
    }
    const float* cp = inb + 4 * tx;
#pragma unroll 2
    for (int k = 0; k < 64; ++k) {
        float4 a = *reinterpret_cast<const float4*>(cp + (k << 8));
        u64 r0 = pk2(fmaxf(a.x, 0.0f));
        u64 r1 = pk2(fmaxf(a.y, 0.0f));
        u64 r2 = pk2(fmaxf(a.z, 0.0f));
        u64 r3 = pk2(fmaxf(a.w, 0.0f));
        const float* wr = Wt + k * PW + ob;
#pragma unroll
        for (int q2 = 0; q2 < 4; ++q2) {
            ulonglong2 w = *reinterpret_cast<const ulonglong2*>(wr + 4 * q2);
            acc[0][2 * q2]     = ffma2(r0, w.x, acc[0][2 * q2]);
            acc[1][2 * q2]     = ffma2(r1, w.x, acc[1][2 * q2]);
            acc[2][2 * q2]     = ffma2(r2, w.x, acc[2][2 * q2]);
            acc[3][2 * q2]     = ffma2(r3, w.x, acc[3][2 * q2]);
            acc[0][2 * q2 + 1] = ffma2(r0, w.y, acc[0][2 * q2 + 1]);
            acc[1][2 * q2 + 1] = ffma2(r1, w.y, acc[1][2 * q2 + 1]);
            acc[2][2 * q2 + 1] = ffma2(r2, w.y, acc[2][2 * q2 + 1]);
            acc[3][2 * q2 + 1] = ffma2(r3, w.y, acc[3][2 * q2 + 1]);
        }
    }
    // register transpose -> conflict-free STS.128 per output row
#pragma unroll
    for (int q = 0; q < 8; ++q) {
        float l0, h0, l1, h1, l2, h2, l3, h3;
        upk2(acc[0][q], l0, h0); upk2(acc[1][q], l1, h1);
        upk2(acc[2][q], l2, h2); upk2(acc[3][q], l3, h3);
        float4 vlo = make_float4(l0, l1, l2, l3);
        float4 vhi = make_float4(h0, h1, h2, h3);
        float* d0 = dst + ((ob + 2 * q) << 8) + 4 * tx;
        float* d1 = dst + ((ob + 2 * q + 1) << 8) + 4 * tx;
        if (ADD) {
            float4 e0 = *reinterpret_cast<const float4*>(d0);
            float4 e1 = *reinterpret_cast<const float4*>(d1);
            vlo.x += e0.x; vlo.y += e0.y; vlo.z += e0.z; vlo.w += e0.w;
            vhi.x += e1.x; vhi.y += e1.y; vhi.z += e1.z; vhi.w += e1.w;
        }
        *reinterpret_cast<float4*>(d0) = vlo;
        *reinterpret_cast<float4*>(d1) = vhi;
    }
}

extern "C" __global__ void __launch_bounds__(THREADS, 1)
nsf_kernel(const float* __restrict__ x,
           const float* __restrict__ W_in,  const float* __restrict__ b_in,
           const float* __restrict__ W_blk, const float* __restrict__ b_blk,
           const float* __restrict__ W_out, const float* __restrict__ b_out,
           float* __restrict__ out, int n) {
    extern __shared__ float sm[];
    float* sWt  = sm + SM_WT;
    float* sWo  = sm + SM_WO;
    float* sWin = sm + SM_WIN;
    float* sbin = sm + SM_BIN;
    float* sbb  = sm + SM_BBLK;
    float* sbo  = sm + SM_BOUT;
    float* sh   = sm + SM_H;
    float* st   = sm + SM_T;

    const int tid = threadIdx.x;
    const int tx  = tid & 63;
    const int ty  = tid >> 6;

    const int gidr = blockIdx.x * COLS + tid;
    const bool valid = (gidr < n);
    const int g = valid ? gidr : (n - 1);

    float z0 = x[3 * g + 0];
    float z1 = x[3 * g + 1];
    float z2 = x[3 * g + 2];
    float lad_total = 0.0f;

    for (int it = 0; it < 8; ++it) {
        __syncthreads();   // previous transform fully consumed weights + panels

        // ---- stage ALL weights for this transform into smem ----
        const float* gW = W_blk + it * 16384;
        for (int idx = tid; idx < 16384; idx += THREADS) {
            int l = idx >> 12, rem = idx & 4095, o = rem >> 6, k = rem & 63;
            sWt[(l * 64 + k) * PW + o] = gW[idx];
        }
        const float* gWo = W_out + it * 74 * 64;
        for (int idx = tid; idx < 74 * 64; idx += THREADS) {
            int o = idx >> 6, k = idx & 63;
            int col = (o < 37) ? o : (o + 3);
            sWo[k * PO + col] = gWo[idx];
        }
        // zero pad cols {37,38,39,77,78,79} of sWo
        for (int idx = tid; idx < 6 * 64; idx += THREADS) {
            int pc = idx % 6, k = idx / 6;
            int col = (pc < 3) ? (37 + pc) : (74 + pc);
            sWo[k * PO + col] = 0.0f;
        }
        if (tid < 64) {
            sWin[tid] = W_in[it * 64 + tid];
            sbin[tid] = b_in[it * 64 + tid];
        }
        sbb[tid] = b_blk[it * 256 + tid];
        if (tid < 74) {
            int col = (tid < 37) ? tid : (tid + 3);
            sbo[col] = b_out[it * 74 + tid];
        }
        if (tid >= 74 && tid < 80) {
            int pc = tid - 74;
            int col = (pc < 3) ? (37 + pc) : (74 + pc);
            sbo[col] = 0.0f;
        }
        __syncthreads();

        // ---- reverse z; split ident/tr ----
        float c = z2, t0 = z1, t1 = z0;

        // h = ident * W_in + b_in   (thread writes its own column)
#pragma unroll 8
        for (int o = 0; o < 64; ++o)
            sh[(o << 8) + tid] = fmaf(c, sWin[o], sbin[o]);
        __syncthreads();

        // ---- two residual blocks ----
        dense_tile<false>(sWt,            sbb,       sh, st, tx, ty); __syncthreads();
        dense_tile<true >(sWt +  64 * PW, sbb +  64, st, sh, tx, ty); __syncthreads();
        dense_tile<false>(sWt + 128 * PW, sbb + 128, sh, st, tx, ty); __syncthreads();
        dense_tile<true >(sWt + 192 * PW, sbb + 192, st, sh, tx, ty); __syncthreads();

        // ---- output layer: thread = 4 pts x 20 param cols ----
        {
            const int ob = 20 * ty;
            u64 acc[4][10];
#pragma unroll
            for (int q = 0; q < 10; ++q) {
                u64 b = *reinterpret_cast<const u64*>(sbo + ob + 2 * q);
                acc[0][q] = b; acc[1][q] = b; acc[2][q] = b; acc[3][q] = b;
            }
            const float* cp = sh + 4 * tx;
#pragma unroll 2
            for (int k = 0; k < 64; ++k) {
                float4 a = *reinterpret_cast<const float4*>(cp + (k << 8));
                u64 r0 = pk2(a.x), r1 = pk2(a.y), r2 = pk2(a.z), r3 = pk2(a.w);
                const float* wr = sWo + k * PO + ob;
#pragma unroll
                for (int q2 = 0; q2 < 5; ++q2) {
                    ulonglong2 w = *reinterpret_cast<const ulonglong2*>(wr + 4 * q2);
                    acc[0][2 * q2]     = ffma2(r0, w.x, acc[0][2 * q2]);
                    acc[1][2 * q2]     = ffma2(r1, w.x, acc[1][2 * q2]);
                    acc[2][2 * q2]     = ffma2(r2, w.x, acc[2][2 * q2]);
                    acc[3][2 * q2]     = ffma2(r3, w.x, acc[3][2 * q2]);
                    acc[0][2 * q2 + 1] = ffma2(r0, w.y, acc[0][2 * q2 + 1]);
                    acc[1][2 * q2 + 1] = ffma2(r1, w.y, acc[1][2 * q2 + 1]);
                    acc[2][2 * q2 + 1] = ffma2(r2, w.y, acc[2][2 * q2 + 1]);
                    acc[3][2 * q2 + 1] = ffma2(r3, w.y, acc[3][2 * q2 + 1]);
                }
            }
            __syncthreads();   // all reads of sh done before scatter writes sh rows

            // scatter params: padded row r -> st rows 0..63, sh rows 0..15
#pragma unroll
            for (int q = 0; q < 10; ++q) {
                float l0, h0, l1, h1, l2, h2, l3, h3;
                upk2(acc[0][q], l0, h0); upk2(acc[1][q], l1, h1);
                upk2(acc[2][q], l2, h2); upk2(acc[3][q], l3, h3);
                float4 vlo = make_float4(l0, l1, l2, l3);
                float4 vhi = make_float4(h0, h1, h2, h3);
                int r0 = ob + 2 * q, r1 = r0 + 1;
                float* p0 = (r0 < 64 ? st + (r0 << 8) : sh + ((r0 - 64) << 8)) + 4 * tx;
                float* p1 = (r1 < 64 ? st + (r1 << 8) : sh + ((r1 - 64) << 8)) + 4 * tx;
                *reinterpret_cast<float4*>(p0) = vlo;
                *reinterpret_cast<float4*>(p1) = vhi;
            }
        }
        __syncthreads();

        // ---- gather own point's params and run splines (column = tid) ----
        float y0, l0, y1, l1;
        {
            float p[37];
#pragma unroll
            for (int r = 0; r < 37; ++r) p[r] = st[(r << 8) + tid];
            {
                bool inside = (t0 >= -TBc) && (t0 <= TBc);
                float xc = fminf(fmaxf(t0, -TBc), TBc);
                int bin = 0;
                float in_cw, in_w, in_ch, in_h;
                {
                    float e[12]; float m = p[0];
#pragma unroll
                    for (int j = 1; j < 12; ++j) m = fmaxf(m, p[j]);
                    float s = 0.0f;
#pragma unroll
                    for (int j = 0; j < 12; ++j) { e[j] = __expf(p[j] - m); s += e[j]; }
                    float ci = 0.988f * __fdividef(1.0f, s);
#pragma unroll
                    for (int j = 0; j < 12; ++j) e[j] = fmaf(e[j], ci, MINc);
                    float run = 0.0f;
#pragma unroll
                    for (int j = 0; j < 12; ++j) {
                        run += e[j];
                        float ks = (j == 11) ? (TBc + 1e-6f) : fmaf(10.0f, run, -TBc);
                        if (xc >= ks) ++bin;
                    }
                    run = 0.0f; float prev = -TBc;
#pragma unroll
                    for (int j = 0; j < 12; ++j) {
                        run += e[j];
                        float right = (j == 11) ? TBc : fmaf(10.0f, run, -TBc);
                        if (j == bin) { in_cw = prev; in_w = right - prev; }
                        prev = right;
                    }
                }
                {
                    float e[12]; float m = p[12];
#pragma unroll
                    for (int j = 1; j < 12; ++j) m = fmaxf(m, p[12 + j]);
                    float s = 0.0f;
#pragma unroll
                    for (int j = 0; j < 12; ++j) { e[j] = __expf(p[12 + j] - m); s += e[j]; }
                    float ci = 0.988f * __fdividef(1.0f, s);
#pragma unroll
                    for (int j = 0; j < 12; ++j) e[j] = fmaf(e[j], ci, MINc);
                    float run = 0.0f; float prev = -TBc;
#pragma unroll
                    for (int j = 0; j < 12; ++j) {
                        run += e[j];
                        float right = (j == 11) ? TBc : fmaf(10.0f, run, -TBc);
                        if (j == bin) { in_ch = prev; in_h = right - prev; }
                        prev = right;
                    }
                }
                float uk = DCONSTf, uk1 = DCONSTf;
#pragma unroll
                for (int j = 1; j <= 12; ++j) {
                    float v = p[23 + j];
                    if (j == bin)     uk  = v;
                    if (j == bin + 1) uk1 = v;
                }
                float dk  = MINc + softplusf(uk);
                float dk1 = MINc + softplusf(uk1);
                float invw  = __fdividef(1.0f, in_w);
                float delta = in_h * invw;
                float theta = (xc - in_cw) * invw;
                float om    = 1.0f - theta;
                float t1m   = theta * om;
                float th2   = theta * theta;
                float num   = in_h * (delta * th2 + dk * t1m);
                float den   = delta + (dk + dk1 - 2.0f * delta) * t1m;
                float yv    = in_ch + __fdividef(num, den);
                float dnum  = (delta * delta) * (dk1 * th2 + 2.0f * delta * t1m + dk * om * om);
                float lad   = __logf(dnum) - 2.0f * __logf(den);
                y0 = inside ? yv : t0;
                l0 = inside ? lad : 0.0f;
            }
        }
        {
            float p[37];
#pragma unroll
            for (int r = 40; r < 64; ++r) p[r - 40] = st[(r << 8) + tid];
#pragma unroll
            for (int r = 64; r < 77; ++r) p[r - 40] = sh[((r - 64) << 8) + tid];
            {
                bool inside = (t1 >= -TBc) && (t1 <= TBc);
                float xc = fminf(fmaxf(t1, -TBc), TBc);
                int bin = 0;
                float in_cw, in_w, in_ch, in_h;
                {
                    float e[12]; float m = p[0];
#pragma unroll
                    for (int j = 1; j < 12; ++j) m = fmaxf(m, p[j]);
                    float s = 0.0f;
#pragma unroll
                    for (int j = 0; j < 12; ++j) { e[j] = __expf(p[j] - m); s += e[j]; }
                    float ci = 0.988f * __fdividef(1.0f, s);
#pragma unroll
                    for (int j = 0; j < 12; ++j) e[j] = fmaf(e[j], ci, MINc);
                    float run = 0.0f;
#pragma unroll
                    for (int j = 0; j < 12; ++j) {
                        run += e[j];
                        float ks = (j == 11) ? (TBc + 1e-6f) : fmaf(10.0f, run, -TBc);
                        if (xc >= ks) ++bin;
                    }
                    run = 0.0f; float prev = -TBc;
#pragma unroll
                    for (int j = 0; j < 12; ++j) {
                        run += e[j];
                        float right = (j == 11) ? TBc : fmaf(10.0f, run, -TBc);
                        if (j == bin) { in_cw = prev; in_w = right - prev; }
                        prev = right;
                    }
                }
                {
                    float e[12]; float m = p[12];
#pragma unroll
                    for (int j = 1; j < 12; ++j) m = fmaxf(m, p[12 + j]);
                    float s = 0.0f;
#pragma unroll
                    for (int j = 0; j < 12; ++j) { e[j] = __expf(p[12 + j] - m); s += e[j]; }
                    float ci = 0.988f * __fdividef(1.0f, s);
#pragma unroll
                    for (int j = 0; j < 12; ++j) e[j] = fmaf(e[j], ci, MINc);
                    float run = 0.0f; float prev = -TBc;
#pragma unroll
                    for (int j = 0; j < 12; ++j) {
                        run += e[j];
                        float right = (j == 11) ? TBc : fmaf(10.0f, run, -TBc);
                        if (j == bin) { in_ch = prev; in_h = right - prev; }
                        prev = right;
                    }
                }
                float uk = DCONSTf, uk1 = DCONSTf;
#pragma unroll
                for (int j = 1; j <= 12; ++j) {
                    float v = p[23 + j];
                    if (j == bin)     uk  = v;
                    if (j == bin + 1) uk1 = v;
                }
                float dk  = MINc + softplusf(uk);
                float dk1 = MINc + softplusf(uk1);
                float invw  = __fdividef(1.0f, in_w);
                float delta = in_h * invw;
                float theta = (xc - in_cw) * invw;
                float om    = 1.0f - theta;
                float t1m   = theta * om;
                float th2   = theta * theta;
                float num   = in_h * (delta * th2 + dk * t1m);
                float den   = delta + (dk + dk1 - 2.0f * delta) * t1m;
                float yv    = in_ch + __fdividef(num, den);
                float dnum  = (delta * delta) * (dk1 * th2 + 2.0f * delta * t1m + dk * om * om);
                float lad   = __logf(dnum) - 2.0f * __logf(den);
                y1 = inside ? yv : t1;
                l1 = inside ? lad : 0.0f;
            }
        }

        z0 = c; z1 = y0; z2 = y1;
        lad_total += l0 + l1;
    }

    if (valid)
        out[gidr] = fmaf(-0.5f, z0 * z0 + z1 * z1 + z2 * z2, LOGZc + lad_total);
}

extern "C" void kernel_launch(void* const* d_in, const int* in_sizes, int n_in,
                              void* d_out, int out_size) {
    const float* x     = (const float*)d_in[0];
    const float* W_in  = (const float*)d_in[1];
    const float* b_in  = (const float*)d_in[2];
    const float* W_blk = (const float*)d_in[3];
    const float* b_blk = (const float*)d_in[4];
    const float* W_out = (const float*)d_in[5];
    const float* b_out = (const float*)d_in[6];
    float* out = (float*)d_out;

    int n = in_sizes[0] / 3;
    cudaFuncSetAttribute(nsf_kernel, cudaFuncAttributeMaxDynamicSharedMemorySize,
                         SMEM_BYTES);
    int blocks = (n + COLS - 1) / COLS;
    nsf_kernel<<<blocks, THREADS, SMEM_BYTES>>>(x, W_in, b_in, W_blk, b_blk,
                                                W_out, b_out, out, n);
}